// round 3
// baseline (speedup 1.0000x reference)
#include <cuda_runtime.h>
#include <math.h>

// Problem constants
#define BB 2
#define SS 2048
#define HH 16
#define DD 64
#define ATTN_SCALE 0.125f        // D^-0.5
#define NEG_BIG   (-1.0e9f)

// Tiling
#define BM 32                    // queries per block
#define BN 64                    // keys per tile
#define NTHREADS 256
#define NWARPS 8
#define QPW (BM / NWARPS)        // 4 queries per warp
#define KT_LD (BN + 2)           // 66: even pad -> float2-aligned, conflict-free reads

__global__ __launch_bounds__(NTHREADS)
void mha_flash_fp32_kernel(const float* __restrict__ q,
                           const float* __restrict__ k,
                           const float* __restrict__ v,
                           const int* __restrict__ mask,   // bool marshalled as int32
                           float* __restrict__ out)
{
    __shared__ float qs[BM][DD];        // 8 KB
    __shared__ float kT[DD][KT_LD];     // ~16.5 KB, transposed K tile
    __shared__ float vs[BN][DD];        // 16 KB

    const int qtile = blockIdx.x;       // 0..S/BM-1
    const int h     = blockIdx.y;       // 0..H-1
    const int b     = blockIdx.z;       // 0..B-1
    const int tid   = threadIdx.x;
    const int warp  = tid >> 5;
    const int lane  = tid & 31;

    const int q0   = qtile * BM;
    const int my_q = q0 + warp * QPW;

    // ---- load Q tile (float4, coalesced) ----
    for (int i = tid; i < BM * DD / 4; i += NTHREADS) {
        const int row = i >> 4;            // /16
        const int c   = (i & 15) << 2;     // *4
        *(float4*)&qs[row][c] =
            *(const float4*)&q[(((size_t)b * SS + q0 + row) * HH + h) * DD + c];
    }

    // per-query online-softmax state; lane owns output dims (2*lane, 2*lane+1)
    float acc0[QPW], acc1[QPW], m_i[QPW], l_i[QPW];
#pragma unroll
    for (int i = 0; i < QPW; i++) {
        acc0[i] = 0.f; acc1[i] = 0.f;
        m_i[i] = -INFINITY; l_i[i] = 0.f;
    }

    const int* mrow[QPW];
#pragma unroll
    for (int i = 0; i < QPW; i++)
        mrow[i] = mask + (((size_t)b * SS + my_q + i) * HH + h) * SS;

    const int ta = 2 * lane;           // this lane's two keys within the tile

    for (int t0 = 0; t0 < SS; t0 += BN) {
        __syncthreads();   // protect previous-iteration smem reads

        // ---- stage K transposed (scalar: coalesced LDG, ~conflict-free STS) ----
        for (int i = tid; i < BN * DD; i += NTHREADS) {
            const int t = i >> 6;          // key within tile
            const int d = i & 63;          // consecutive tid -> consecutive d (coalesced)
            kT[d][t] = k[(((size_t)b * SS + t0 + t) * HH + h) * DD + d];
        }
        // ---- stage V row-major (float4) ----
        for (int i = tid; i < BN * DD / 4; i += NTHREADS) {
            const int t = i >> 4;
            const int c = (i & 15) << 2;
            *(float4*)&vs[t][c] =
                *(const float4*)&v[(((size_t)b * SS + t0 + t) * HH + h) * DD + c];
        }
        __syncthreads();

        // ---- scores: lane = key pair, shared q broadcast ----
        float s0[QPW], s1[QPW];
#pragma unroll
        for (int i = 0; i < QPW; i++) { s0[i] = 0.f; s1[i] = 0.f; }

#pragma unroll
        for (int d = 0; d < DD; d++) {
            const float2 kk = *(const float2*)&kT[d][ta];
#pragma unroll
            for (int i = 0; i < QPW; i++) {
                const float qv = qs[warp * QPW + i][d];   // smem broadcast
                s0[i] += qv * kk.x;
                s1[i] += qv * kk.y;
            }
        }

        // ---- mask + online softmax update ----
        float p0[QPW], p1[QPW];
#pragma unroll
        for (int i = 0; i < QPW; i++) {
            const int2 mm = *(const int2*)(mrow[i] + t0 + ta);
            float sa = mm.x ? s0[i] * ATTN_SCALE : NEG_BIG;
            float sb = mm.y ? s1[i] * ATTN_SCALE : NEG_BIG;

            float mx = fmaxf(sa, sb);
#pragma unroll
            for (int o = 16; o; o >>= 1)
                mx = fmaxf(mx, __shfl_xor_sync(0xFFFFFFFFu, mx, o));

            const float m_new = fmaxf(m_i[i], mx);
            const float corr  = __expf(m_i[i] - m_new);
            const float pa = __expf(sa - m_new);
            const float pb = __expf(sb - m_new);

            float ps = pa + pb;
#pragma unroll
            for (int o = 16; o; o >>= 1)
                ps += __shfl_xor_sync(0xFFFFFFFFu, ps, o);

            l_i[i]  = l_i[i] * corr + ps;
            m_i[i]  = m_new;
            acc0[i] *= corr;
            acc1[i] *= corr;
            p0[i] = pa; p1[i] = pb;
        }

        // ---- PV: lane = dim pair, broadcast p via shuffle ----
#pragma unroll
        for (int t = 0; t < BN; t++) {
            const int src = t >> 1;
            const float2 vv = *(const float2*)&vs[t][ta];
#pragma unroll
            for (int i = 0; i < QPW; i++) {
                const float pt = __shfl_sync(0xFFFFFFFFu,
                                             (t & 1) ? p1[i] : p0[i], src);
                acc0[i] += pt * vv.x;
                acc1[i] += pt * vv.y;
            }
        }
    }

    // ---- epilogue: normalize, write out[b][q][h*64 + d] ----
#pragma unroll
    for (int i = 0; i < QPW; i++) {
        const float inv = 1.0f / l_i[i];
        float2 o;
        o.x = acc0[i] * inv;
        o.y = acc1[i] * inv;
        *(float2*)&out[(((size_t)b * SS + my_q + i) * HH + h) * DD + ta] = o;
    }
}

extern "C" void kernel_launch(void* const* d_in, const int* in_sizes, int n_in,
                              void* d_out, int out_size)
{
    (void)in_sizes; (void)n_in; (void)out_size;
    const float* q = (const float*)d_in[0];
    const float* k = (const float*)d_in[1];
    const float* v = (const float*)d_in[2];
    const int*   mask = (const int*)d_in[3];
    float* out = (float*)d_out;

    dim3 grid(SS / BM, HH, BB);
    dim3 block(NTHREADS);
    mha_flash_fp32_kernel<<<grid, block>>>(q, k, v, mask, out);
}